// round 16
// baseline (speedup 1.0000x reference)
#include <cuda_runtime.h>
#include <cuda_bf16.h>
#include <mma.h>
#include <math.h>

using namespace nvcuda;

#define NROWS (64*9*374)      // 215424 rows of F=128
#define BT    (64*9)          // 576 (b,t) groups
#define RR    374
#define KSEL  299
#define NBLK1 (NROWS/64)      // 3366 64-row tiles (exact)
#define EPS_TINY 1.17549435082228750797e-38f

typedef unsigned long long u64;
typedef unsigned int u32;
typedef unsigned short u16;

// scratch (static device memory — no runtime allocation)
__device__ __align__(16) float g_acc32[(size_t)NROWS*32]; // local @ w2[:64]
__device__ float g_part[NBLK1*128];                       // per-tile hi partials
__device__ float g_gcon[BT*32];                           // glob @ w2[64:,:]
__device__ float g_scores[NROWS];                         // score + gumbel
__device__ __align__(16) __nv_bfloat16 g_w1h[128*128];    // w1 bf16 limbs
__device__ __align__(16) __nv_bfloat16 g_w1m[128*128];
__device__ __align__(16) __nv_bfloat16 g_w1l[128*128];

// ---- helpers --------------------------------------------------------------
__device__ __forceinline__ u64 fma2(u64 a, u64 b, u64 c) {
    u64 d; asm("fma.rn.f32x2 %0,%1,%2,%3;" : "=l"(d) : "l"(a), "l"(b), "l"(c));
    return d;
}
__device__ __forceinline__ void upk2(u64 v, float& lo, float& hi) {
    asm("mov.b64 {%0,%1},%2;" : "=f"(lo), "=f"(hi) : "l"(v));
}
__device__ __forceinline__ float frcp(float x) {
    float r; asm("rcp.approx.ftz.f32 %0,%1;" : "=f"(r) : "f"(x));
    return r;
}
__device__ __forceinline__ float warp_sum(float v) {
    #pragma unroll
    for (int o = 16; o; o >>= 1) v += __shfl_xor_sync(0xffffffffu, v, o);
    return v;
}
__device__ __forceinline__ float gelu_exact(float x) {
    float z = x * 0.70710678118654752440f;
    float s = fabsf(z);
    float t = frcp(fmaf(0.3275911f, s, 1.0f));
    float p = t * fmaf(t, fmaf(t, fmaf(t, fmaf(t, 1.061405429f, -1.453152027f),
                                       1.421413741f), -0.284496736f), 0.254829592f);
    float e = __expf(-s * s);
    float er = copysignf(fmaf(-p, e, 1.0f), z);
    return 0.5f * x * (1.0f + er);
}
// 3-limb bf16 split: v = h + m + l + O(2^-27 v)
__device__ __forceinline__ void split3(float v, u16& h, u16& m, u16& l) {
    __nv_bfloat16 bh = __float2bfloat16(v);
    float r1 = v - __bfloat162float(bh);
    __nv_bfloat16 bm = __float2bfloat16(r1);
    float r2 = r1 - __bfloat162float(bm);
    __nv_bfloat16 bl = __float2bfloat16(r2);
    h = __bfloat16_as_ushort(bh);
    m = __bfloat16_as_ushort(bm);
    l = __bfloat16_as_ushort(bl);
}

// smem layout (bytes)
#define LDA 136                 // bf16 leading dim (mult of 8)
#define LDH 72                  // hloc f32 leading dim
#define LDB2 68                 // hbuf f32 leading dim
#define SM_AH 0                 // 64*136*2 = 17408
#define SM_AM 17408
#define SM_AL 34816
#define SM_BH 52224             // 128*136*2 = 34816 each
#define SM_BM 87040
#define SM_BL 121856
#define SM_HLOC 156672          // 64*72*4 = 18432
#define SM_HBUF 175104          // 64*68*4 = 17408
#define SM_W2T  192512          // 32*66*4 = 8448
#define SM_B1S  200960          // 512
#define SM_TOTAL 201472

// ---------------------------------------------------------------------------
// Kernel 0: split w1 into 3 bf16 limbs once (shared by all k1 tiles).
// ---------------------------------------------------------------------------
__global__ void __launch_bounds__(256) k0_split_w1(const float* __restrict__ w1)
{
    int id = blockIdx.x*256 + threadIdx.x;     // 64 blocks -> 16384 values
    u16 h, m, l;
    split3(w1[id], h, m, l);
    g_w1h[id] = __ushort_as_bfloat16(h);
    g_w1m[id] = __ushort_as_bfloat16(m);
    g_w1l[id] = __ushort_as_bfloat16(l);
}

// ---------------------------------------------------------------------------
// Kernel 1: LN -> 3-limb bf16 HMMA GEMM1 (64x128x128, 6 terms) -> GELU ->
// glob partials + fused FFMA2 stage-2 GEMM. One 64-row tile per block.
// D = Ah*Bh + Ah*Bm + Am*Bh + Ah*Bl + Am*Bm + Al*Bh  (error ~2^-26).
// ---------------------------------------------------------------------------
__global__ void __launch_bounds__(256, 1)
k1_ln_gemm1(const float* __restrict__ x, const float* __restrict__ ln_w,
            const float* __restrict__ ln_b, const float* __restrict__ b1,
            const float* __restrict__ w2)
{
    extern __shared__ char smc[];
    __nv_bfloat16* Ah = (__nv_bfloat16*)(smc + SM_AH);
    __nv_bfloat16* Am = (__nv_bfloat16*)(smc + SM_AM);
    __nv_bfloat16* Al = (__nv_bfloat16*)(smc + SM_AL);
    __nv_bfloat16* Bh = (__nv_bfloat16*)(smc + SM_BH);
    __nv_bfloat16* Bm = (__nv_bfloat16*)(smc + SM_BM);
    __nv_bfloat16* Bl = (__nv_bfloat16*)(smc + SM_BL);
    float* hloc = (float*)(smc + SM_HLOC);
    float* hbuf = (float*)(smc + SM_HBUF);
    float* w2t  = (float*)(smc + SM_W2T);
    float* b1s  = (float*)(smc + SM_B1S);

    const int t = threadIdx.x;
    const int w = t >> 5, lane = t & 31;
    const int R0 = blockIdx.x * 64;

    // copy w1 limbs -> smem: 4096 u64 per limb (128 rows x 32 u64), pad LDA=136
    {
        const u64* sh = (const u64*)g_w1h;
        const u64* sm_ = (const u64*)g_w1m;
        const u64* sl = (const u64*)g_w1l;
        #pragma unroll
        for (int i = 0; i < 16; i++) {
            int id = i*256 + t;              // u64 id: k = id/32, q = id%32
            int k = id >> 5, q = id & 31;
            size_t off = (size_t)(k*LDA + q*4)*2;
            *(u64*)(smc + SM_BH + off) = sh[id];
            *(u64*)(smc + SM_BM + off) = sm_[id];
            *(u64*)(smc + SM_BL + off) = sl[id];
        }
    }
    // stage w2t + b1s
    #pragma unroll
    for (int i = 0; i < 8; i++) {
        int id = i*256 + t;
        w2t[(id & 31)*66 + (id >> 5)] = w2[id];
    }
    if (t < 128) b1s[t] = b1[t];

    // LN: 8 warps x 8 rows -> A limbs (row-major, ldm 136)
    {
        float4 lw = ((const float4*)ln_w)[lane];
        float4 lb = ((const float4*)ln_b)[lane];
        #pragma unroll
        for (int rr = 0; rr < 8; rr++) {
            int r = w*8 + rr;
            float4 xv = ((const float4*)x)[(size_t)(R0 + r)*32 + lane];
            float s = warp_sum(xv.x + xv.y + xv.z + xv.w);
            float m = s * (1.0f/128.0f);
            float dx = xv.x - m, dy = xv.y - m, dz = xv.z - m, dw = xv.w - m;
            float q = warp_sum(dx*dx + dy*dy + dz*dz + dw*dw);
            float rs = rsqrtf(q * (1.0f/128.0f) + 1e-5f);
            float y[4];
            y[0] = dx*rs*lw.x + lb.x;
            y[1] = dy*rs*lw.y + lb.y;
            y[2] = dz*rs*lw.z + lb.z;
            y[3] = dw*rs*lw.w + lb.w;
            u64 ph = 0, pm = 0, pl = 0;
            #pragma unroll
            for (int j = 0; j < 4; j++) {
                u16 h, mm, l;
                split3(y[j], h, mm, l);
                ph |= (u64)h  << (16*j);
                pm |= (u64)mm << (16*j);
                pl |= (u64)l  << (16*j);
            }
            size_t off = (size_t)(r*LDA + lane*4)*2;
            *(u64*)(smc + SM_AH + off) = ph;
            *(u64*)(smc + SM_AM + off) = pm;
            *(u64*)(smc + SM_AL + off) = pl;
        }
    }
    __syncthreads();

    // wmma GEMM: warp tile 32 rows x 32 cols (2x4 warp grid)
    {
        const int r0 = (w >> 2) * 32;
        const int c0 = (w & 3) * 32;
        wmma::fragment<wmma::accumulator, 16, 16, 16, float> acc[2][2];
        #pragma unroll
        for (int i = 0; i < 2; i++)
            #pragma unroll
            for (int n = 0; n < 2; n++) wmma::fill_fragment(acc[i][n], 0.0f);

        const __nv_bfloat16* As[6] = {Ah, Ah, Am, Ah, Am, Al};
        const __nv_bfloat16* Bs[6] = {Bh, Bm, Bh, Bl, Bm, Bh};
        #pragma unroll
        for (int term = 0; term < 6; term++) {
            const __nv_bfloat16* Ab = As[term];
            const __nv_bfloat16* Bb = Bs[term];
            #pragma unroll
            for (int k8 = 0; k8 < 8; k8++) {
                wmma::fragment<wmma::matrix_a, 16, 16, 16, __nv_bfloat16,
                               wmma::row_major> a0, a1;
                wmma::load_matrix_sync(a0, Ab + (size_t)r0*LDA + k8*16, LDA);
                wmma::load_matrix_sync(a1, Ab + (size_t)(r0+16)*LDA + k8*16, LDA);
                #pragma unroll
                for (int n = 0; n < 2; n++) {
                    wmma::fragment<wmma::matrix_b, 16, 16, 16, __nv_bfloat16,
                                   wmma::row_major> bf;
                    wmma::load_matrix_sync(bf, Bb + (size_t)(k8*16)*LDA + c0 + n*16, LDA);
                    wmma::mma_sync(acc[0][n], a0, bf, acc[0][n]);
                    wmma::mma_sync(acc[1][n], a1, bf, acc[1][n]);
                }
            }
        }
        // store: cols<64 -> hloc (ldm 72), cols>=64 -> hbuf (ldm 68)
        #pragma unroll
        for (int i = 0; i < 2; i++) {
            #pragma unroll
            for (int n = 0; n < 2; n++) {
                int rr = r0 + 16*i, cc = c0 + 16*n;
                if (cc < 64)
                    wmma::store_matrix_sync(hloc + (size_t)rr*LDH + cc, acc[i][n],
                                            LDH, wmma::mem_row_major);
                else
                    wmma::store_matrix_sync(hbuf + (size_t)rr*LDB2 + (cc - 64), acc[i][n],
                                            LDB2, wmma::mem_row_major);
            }
        }
    }
    __syncthreads();

    // in-place bias + gelu (16 values per thread per half)
    #pragma unroll 4
    for (int idx = t; idx < 4096; idx += 256) {
        int r = idx >> 6, c = idx & 63;
        hloc[r*LDH + c]  = gelu_exact(hloc[r*LDH + c]  + b1s[c]);
        hbuf[r*LDB2 + c] = gelu_exact(hbuf[r*LDB2 + c] + b1s[64 + c]);
    }
    __syncthreads();

    // glob partials from hbuf (64 rows)
    {
        int g0 = R0 / RR;
        int bnd = (g0 + 1)*RR - R0;
        if (bnd > 64) bnd = 64;
        if (t < 128) {
            int side = t >> 6, col = t & 63;
            int r0 = side ? bnd : 0;
            int r1 = side ? 64 : bnd;
            float s = 0.0f;
            for (int r = r0; r < r1; r++) s += hbuf[r*LDB2 + col];
            g_part[blockIdx.x*128 + side*64 + col] = s;
        }
    }

    // stage-2 GEMM (FFMA2): hloc[64x64] @ w2t -> g_acc32
    {
        const int ty = t >> 4, tx = t & 15;     // rows ty*4..+3, cols {tx, tx+16}
        u64 acc2[4][2];
        #pragma unroll
        for (int i = 0; i < 4; i++) { acc2[i][0] = 0ULL; acc2[i][1] = 0ULL; }
        const u64* hu   = (const u64*)hloc;     // row stride 36 u64 (LDH=72)
        const u64* w2u0 = (const u64*)(w2t + tx*66);
        const u64* w2u1 = (const u64*)(w2t + (tx+16)*66);
        #pragma unroll 8
        for (int k2 = 0; k2 < 32; k2++) {
            u64 b0 = w2u0[k2], b1v = w2u1[k2];
            #pragma unroll
            for (int i = 0; i < 4; i++) {
                u64 a = hu[(ty*4 + i)*36 + k2];
                acc2[i][0] = fma2(a, b0,  acc2[i][0]);
                acc2[i][1] = fma2(a, b1v, acc2[i][1]);
            }
        }
        #pragma unroll
        for (int i = 0; i < 4; i++) {
            size_t rg = (size_t)(R0 + ty*4 + i);
            float lo, hi;
            upk2(acc2[i][0], lo, hi);
            g_acc32[rg*32 + tx]      = lo + hi;
            upk2(acc2[i][1], lo, hi);
            g_acc32[rg*32 + tx + 16] = lo + hi;
        }
    }
}

// ---------------------------------------------------------------------------
// Kernel glob: combine per-tile partials -> mean -> glob @ w2[64:,:].
// (64-row tiles.)
// ---------------------------------------------------------------------------
__global__ void __launch_bounds__(64) k_glob(const float* __restrict__ w2)
{
    __shared__ float gl[64];
    const int g = blockIdx.x, c = threadIdx.x;
    const int b_start = (g * RR) >> 6;
    const int b_end   = (g * RR + RR - 1) >> 6;
    float s = 0.0f;
    for (int b = b_start; b <= b_end; b++) {
        int side = g - (b * 64) / RR;     // 0 or 1 by construction
        s += g_part[b*128 + side*64 + c];
    }
    gl[c] = s * (1.0f/374.0f);
    __syncthreads();
    if (c < 32) {
        float a = 0.0f;
        #pragma unroll
        for (int k = 0; k < 64; k++) a += gl[k] * w2[(64 + k)*32 + c];
        g_gcon[g*32 + c] = a;
    }
}

// ---------------------------------------------------------------------------
// Kernel 2 (elementwise): gelu(acc32 + gcon + b2) -> w3 head -> softmax ->
// score + Gumbel -> g_scores.
// ---------------------------------------------------------------------------
__global__ void __launch_bounds__(256) k2_scores(
    const float* __restrict__ b2, const float* __restrict__ w3,
    const float* __restrict__ b3, const float* __restrict__ u)
{
    __shared__ float b2s[32];
    __shared__ float w3s[64];
    __shared__ float b3s[2];
    const int t = threadIdx.x;
    if (t < 32) b2s[t] = b2[t];
    if (t < 64) w3s[t] = w3[t];
    if (t < 2)  b3s[t] = b3[t];
    __syncthreads();

    const int e = blockIdx.x*256 + t;
    if (e >= NROWS) return;
    const int bt = e / RR;
    const float* gc = g_gcon + bt*32;

    float z0 = b3s[0], z1 = b3s[1];
    const float4* ap = (const float4*)(g_acc32 + (size_t)e*32);
    #pragma unroll
    for (int q = 0; q < 8; q++) {
        float4 a = ap[q];
        int c = q*4;
        float h0 = gelu_exact(a.x + b2s[c]   + gc[c]);
        float h1 = gelu_exact(a.y + b2s[c+1] + gc[c+1]);
        float h2 = gelu_exact(a.z + b2s[c+2] + gc[c+2]);
        float h3 = gelu_exact(a.w + b2s[c+3] + gc[c+3]);
        z0 += h0*w3s[2*c]   + h1*w3s[2*c+2] + h2*w3s[2*c+4] + h3*w3s[2*c+6];
        z1 += h0*w3s[2*c+1] + h1*w3s[2*c+3] + h2*w3s[2*c+5] + h3*w3s[2*c+7];
    }
    float m  = fmaxf(z0, z1);
    float e0 = expf(z0 - m), e1 = expf(z1 - m);
    float score = e1 / (e0 + e1);
    float uu  = u[e];
    float gum = -logf(-logf(uu));
    g_scores[e] = score + gum;
}

// ---------------------------------------------------------------------------
// Kernel 3: 299-step subset-operator scan, one warp per (b,t).
// ---------------------------------------------------------------------------
__global__ void __launch_bounds__(32) k3_scan(float* __restrict__ out)
{
    const int bt = blockIdx.x, lane = threadIdx.x;

    float ex[12], kh[12];
    #pragma unroll
    for (int j = 0; j < 12; j++) {
        int idx = j*32 + lane;
        ex[j] = (idx < RR) ? expf(g_scores[(size_t)bt*RR + idx]) : 0.0f;
        kh[j] = 0.0f;
    }

    #pragma unroll 1
    for (int it = 0; it < KSEL - 1; it++) {
        float z = (((ex[0] + ex[1]) + (ex[2] + ex[3])) +
                   ((ex[4] + ex[5]) + (ex[6] + ex[7]))) +
                  ((ex[8] + ex[9]) + (ex[10] + ex[11]));
        #pragma unroll
        for (int o = 16; o; o >>= 1) z += __shfl_xor_sync(0xffffffffu, z, o);
        float rinv = frcp(z);
        #pragma unroll
        for (int j = 0; j < 12; j++) {
            kh[j] = fmaf(ex[j], rinv, kh[j]);
            float m = fmaxf(fmaf(-ex[j], rinv, 1.0f), EPS_TINY);
            ex[j] *= m;
        }
    }
    {
        float z = (((ex[0] + ex[1]) + (ex[2] + ex[3])) +
                   ((ex[4] + ex[5]) + (ex[6] + ex[7]))) +
                  ((ex[8] + ex[9]) + (ex[10] + ex[11]));
        #pragma unroll
        for (int o = 16; o; o >>= 1) z += __shfl_xor_sync(0xffffffffu, z, o);
        float rinv = frcp(z);
        #pragma unroll
        for (int j = 0; j < 12; j++) kh[j] = fmaf(ex[j], rinv, kh[j]);
    }

    #pragma unroll
    for (int j = 0; j < 12; j++) {
        int idx = j*32 + lane;
        if (idx < RR) out[(size_t)bt*RR + idx] = kh[j];
    }
}

// ---------------------------------------------------------------------------
// Kernel 4: stable top-K rank (value desc, ties -> lower index).
// ---------------------------------------------------------------------------
__global__ void __launch_bounds__(384) k4_rank(float* __restrict__ out)
{
    __shared__ float ks[RR];
    const int bt = blockIdx.x, t = threadIdx.x;
    if (t < RR) ks[t] = out[(size_t)bt*RR + t];
    __syncthreads();
    if (t >= RR) return;
    const float mine = ks[t];
    int rank = 0;
    #pragma unroll 4
    for (int i = 0; i < RR; i++) {
        float kv = ks[i];
        rank += (kv > mine) || (kv == mine && i < t);
    }
    if (rank < KSEL)
        out[(size_t)NROWS + (size_t)bt*KSEL + rank] = (float)t;
}

// ---------------------------------------------------------------------------
extern "C" void kernel_launch(void* const* d_in, const int* in_sizes, int n_in,
                              void* d_out, int out_size)
{
    const float* x   = (const float*)d_in[0];
    const float* u   = (const float*)d_in[1];
    const float* lnw = (const float*)d_in[2];
    const float* lnb = (const float*)d_in[3];
    const float* w1  = (const float*)d_in[4];
    const float* b1  = (const float*)d_in[5];
    const float* w2  = (const float*)d_in[6];
    const float* b2  = (const float*)d_in[7];
    const float* w3  = (const float*)d_in[8];
    const float* b3  = (const float*)d_in[9];
    float* out = (float*)d_out;

    cudaFuncSetAttribute(k1_ln_gemm1, cudaFuncAttributeMaxDynamicSharedMemorySize,
                         SM_TOTAL);

    k0_split_w1<<<64, 256>>>(w1);
    k1_ln_gemm1<<<NBLK1, 256, SM_TOTAL>>>(x, lnw, lnb, b1, w2);
    k_glob<<<BT, 64>>>(w2);
    k2_scores<<<(NROWS + 255)/256, 256>>>(b2, w3, b3, u);
    k3_scan<<<BT, 32>>>(out);
    k4_rank<<<BT, 384>>>(out);
}

// round 17
// speedup vs baseline: 1.1987x; 1.1987x over previous
#include <cuda_runtime.h>
#include <cuda_bf16.h>
#include <mma.h>
#include <math.h>

using namespace nvcuda;

#define NROWS (64*9*374)      // 215424 rows of F=128
#define BT    (64*9)          // 576 (b,t) groups
#define RR    374
#define KSEL  299
#define NBLK1 (NROWS/128)     // 1683 128-row tiles (exact)
#define EPS_TINY 1.17549435082228750797e-38f

typedef unsigned long long u64;
typedef unsigned int u32;
typedef unsigned short u16;

// scratch (static device memory — no runtime allocation)
__device__ __align__(16) float g_acc32[(size_t)NROWS*32]; // local @ w2[:64]
__device__ float g_part[NBLK1*128];                       // per-tile hi partials
__device__ float g_gcon[BT*32];                           // glob @ w2[64:,:]
__device__ float g_scores[NROWS];                         // score + gumbel
__device__ __align__(16) __nv_bfloat16 g_w1h[128*128];    // w1 bf16 limbs
__device__ __align__(16) __nv_bfloat16 g_w1m[128*128];
__device__ __align__(16) __nv_bfloat16 g_w1l[128*128];

// ---- helpers --------------------------------------------------------------
__device__ __forceinline__ u64 fma2(u64 a, u64 b, u64 c) {
    u64 d; asm("fma.rn.f32x2 %0,%1,%2,%3;" : "=l"(d) : "l"(a), "l"(b), "l"(c));
    return d;
}
__device__ __forceinline__ void upk2(u64 v, float& lo, float& hi) {
    asm("mov.b64 {%0,%1},%2;" : "=f"(lo), "=f"(hi) : "l"(v));
}
__device__ __forceinline__ float frcp(float x) {
    float r; asm("rcp.approx.ftz.f32 %0,%1;" : "=f"(r) : "f"(x));
    return r;
}
__device__ __forceinline__ float warp_sum(float v) {
    #pragma unroll
    for (int o = 16; o; o >>= 1) v += __shfl_xor_sync(0xffffffffu, v, o);
    return v;
}
__device__ __forceinline__ float gelu_exact(float x) {
    float z = x * 0.70710678118654752440f;
    float s = fabsf(z);
    float t = frcp(fmaf(0.3275911f, s, 1.0f));
    float p = t * fmaf(t, fmaf(t, fmaf(t, fmaf(t, 1.061405429f, -1.453152027f),
                                       1.421413741f), -0.284496736f), 0.254829592f);
    float e = __expf(-s * s);
    float er = copysignf(fmaf(-p, e, 1.0f), z);
    return 0.5f * x * (1.0f + er);
}
// 3-limb bf16 split: v = h + m + l + O(2^-27 v)
__device__ __forceinline__ void split3(float v, u16& h, u16& m, u16& l) {
    __nv_bfloat16 bh = __float2bfloat16(v);
    float r1 = v - __bfloat162float(bh);
    __nv_bfloat16 bm = __float2bfloat16(r1);
    float r2 = r1 - __bfloat162float(bm);
    __nv_bfloat16 bl = __float2bfloat16(r2);
    h = __bfloat16_as_ushort(bh);
    m = __bfloat16_as_ushort(bm);
    l = __bfloat16_as_ushort(bl);
}

// smem layout (bytes)
#define LDA 136                 // bf16 leading dim (mult of 8)
#define LDH 72                  // hloc f32 leading dim
#define LDB2 68                 // hbuf f32 leading dim
#define SM_AH 0                 // 128*136*2 = 34816 each
#define SM_AM 34816
#define SM_AL 69632
#define SM_BH 104448
#define SM_BM 139264
#define SM_BL 174080
#define SM_W2T  208896          // 32*66*4 = 8448
#define SM_B1S  217344          // 512
#define SM_TOTAL 217856
// epilogue buffers overlay A-limb region (A dead after MMA)
#define SM_HLOC 0               // 128*72*4 = 36864
#define SM_HBUF 36864           // 128*68*4 = 34816

// ---------------------------------------------------------------------------
// Kernel 0: split w1 into 3 bf16 limbs once (shared by all k1 tiles).
// ---------------------------------------------------------------------------
__global__ void __launch_bounds__(256) k0_split_w1(const float* __restrict__ w1)
{
    int id = blockIdx.x*256 + threadIdx.x;     // 64 blocks -> 16384 values
    u16 h, m, l;
    split3(w1[id], h, m, l);
    g_w1h[id] = __ushort_as_bfloat16(h);
    g_w1m[id] = __ushort_as_bfloat16(m);
    g_w1l[id] = __ushort_as_bfloat16(l);
}

// ---------------------------------------------------------------------------
// Kernel 1: LN -> 3-limb bf16 HMMA GEMM1 (128x128x128, 6 terms) -> GELU ->
// glob partials + fused FFMA2 stage-2 GEMM. One 128-row tile per block.
// Warp grid 4x2: warp tile 32 rows x 64 cols, acc[2][4].
// Loop: k8 outer, per k8 load 6 a-frags + per-limb b-frags, 48 mma.
// ---------------------------------------------------------------------------
__global__ void __launch_bounds__(256, 1)
k1_ln_gemm1(const float* __restrict__ x, const float* __restrict__ ln_w,
            const float* __restrict__ ln_b, const float* __restrict__ b1,
            const float* __restrict__ w2)
{
    extern __shared__ char smc[];
    __nv_bfloat16* Ah = (__nv_bfloat16*)(smc + SM_AH);
    __nv_bfloat16* Am = (__nv_bfloat16*)(smc + SM_AM);
    __nv_bfloat16* Al = (__nv_bfloat16*)(smc + SM_AL);
    __nv_bfloat16* Bh = (__nv_bfloat16*)(smc + SM_BH);
    __nv_bfloat16* Bm = (__nv_bfloat16*)(smc + SM_BM);
    __nv_bfloat16* Bl = (__nv_bfloat16*)(smc + SM_BL);
    float* hloc = (float*)(smc + SM_HLOC);
    float* hbuf = (float*)(smc + SM_HBUF);
    float* w2t  = (float*)(smc + SM_W2T);
    float* b1s  = (float*)(smc + SM_B1S);

    const int t = threadIdx.x;
    const int w = t >> 5, lane = t & 31;
    const int R0 = blockIdx.x * 128;

    // copy w1 limbs -> smem: 4096 u64 per limb (128 rows x 32 u64), pad LDA=136
    {
        const u64* sh = (const u64*)g_w1h;
        const u64* sm_ = (const u64*)g_w1m;
        const u64* sl = (const u64*)g_w1l;
        #pragma unroll
        for (int i = 0; i < 16; i++) {
            int id = i*256 + t;              // u64 id: k = id/32, q = id%32
            int k = id >> 5, q = id & 31;
            size_t off = (size_t)(k*LDA + q*4)*2;
            *(u64*)(smc + SM_BH + off) = sh[id];
            *(u64*)(smc + SM_BM + off) = sm_[id];
            *(u64*)(smc + SM_BL + off) = sl[id];
        }
    }
    // stage w2t + b1s
    #pragma unroll
    for (int i = 0; i < 8; i++) {
        int id = i*256 + t;
        w2t[(id & 31)*66 + (id >> 5)] = w2[id];
    }
    if (t < 128) b1s[t] = b1[t];

    // LN: 8 warps x 16 rows -> A limbs (row-major, ldm 136)
    {
        float4 lw = ((const float4*)ln_w)[lane];
        float4 lb = ((const float4*)ln_b)[lane];
        #pragma unroll
        for (int rr = 0; rr < 16; rr++) {
            int r = w*16 + rr;
            float4 xv = ((const float4*)x)[(size_t)(R0 + r)*32 + lane];
            float s = warp_sum(xv.x + xv.y + xv.z + xv.w);
            float m = s * (1.0f/128.0f);
            float dx = xv.x - m, dy = xv.y - m, dz = xv.z - m, dw = xv.w - m;
            float q = warp_sum(dx*dx + dy*dy + dz*dz + dw*dw);
            float rs = rsqrtf(q * (1.0f/128.0f) + 1e-5f);
            float y[4];
            y[0] = dx*rs*lw.x + lb.x;
            y[1] = dy*rs*lw.y + lb.y;
            y[2] = dz*rs*lw.z + lb.z;
            y[3] = dw*rs*lw.w + lb.w;
            u64 ph = 0, pm = 0, pl = 0;
            #pragma unroll
            for (int j = 0; j < 4; j++) {
                u16 h, mm, l;
                split3(y[j], h, mm, l);
                ph |= (u64)h  << (16*j);
                pm |= (u64)mm << (16*j);
                pl |= (u64)l  << (16*j);
            }
            size_t off = (size_t)(r*LDA + lane*4)*2;
            *(u64*)(smc + SM_AH + off) = ph;
            *(u64*)(smc + SM_AM + off) = pm;
            *(u64*)(smc + SM_AL + off) = pl;
        }
    }
    __syncthreads();

    // wmma GEMM: warp tile 32 rows x 64 cols (4x2 warp grid)
    {
        const int r0 = (w >> 1) * 32;
        const int c0 = (w & 1) * 64;
        wmma::fragment<wmma::accumulator, 16, 16, 16, float> acc[2][4];
        #pragma unroll
        for (int i = 0; i < 2; i++)
            #pragma unroll
            for (int n = 0; n < 4; n++) wmma::fill_fragment(acc[i][n], 0.0f);

        typedef wmma::fragment<wmma::matrix_a, 16, 16, 16, __nv_bfloat16,
                               wmma::row_major> FragA;
        typedef wmma::fragment<wmma::matrix_b, 16, 16, 16, __nv_bfloat16,
                               wmma::row_major> FragB;

        #pragma unroll
        for (int k8 = 0; k8 < 8; k8++) {
            const size_t ko = (size_t)k8 * 16;
            FragA aH0, aH1, aM0, aM1, aL0, aL1;
            wmma::load_matrix_sync(aH0, Ah + (size_t)r0*LDA + ko, LDA);
            wmma::load_matrix_sync(aH1, Ah + (size_t)(r0+16)*LDA + ko, LDA);
            wmma::load_matrix_sync(aM0, Am + (size_t)r0*LDA + ko, LDA);
            wmma::load_matrix_sync(aM1, Am + (size_t)(r0+16)*LDA + ko, LDA);
            wmma::load_matrix_sync(aL0, Al + (size_t)r0*LDA + ko, LDA);
            wmma::load_matrix_sync(aL1, Al + (size_t)(r0+16)*LDA + ko, LDA);

            // b-limb Bh: terms hh(aH), mh(aM), lh(aL)
            #pragma unroll
            for (int n = 0; n < 4; n++) {
                FragB bf;
                wmma::load_matrix_sync(bf, Bh + ko*LDA + c0 + n*16, LDA);
                wmma::mma_sync(acc[0][n], aH0, bf, acc[0][n]);
                wmma::mma_sync(acc[1][n], aH1, bf, acc[1][n]);
                wmma::mma_sync(acc[0][n], aM0, bf, acc[0][n]);
                wmma::mma_sync(acc[1][n], aM1, bf, acc[1][n]);
                wmma::mma_sync(acc[0][n], aL0, bf, acc[0][n]);
                wmma::mma_sync(acc[1][n], aL1, bf, acc[1][n]);
            }
            // b-limb Bm: terms hm(aH), mm(aM)
            #pragma unroll
            for (int n = 0; n < 4; n++) {
                FragB bf;
                wmma::load_matrix_sync(bf, Bm + ko*LDA + c0 + n*16, LDA);
                wmma::mma_sync(acc[0][n], aH0, bf, acc[0][n]);
                wmma::mma_sync(acc[1][n], aH1, bf, acc[1][n]);
                wmma::mma_sync(acc[0][n], aM0, bf, acc[0][n]);
                wmma::mma_sync(acc[1][n], aM1, bf, acc[1][n]);
            }
            // b-limb Bl: term hl(aH)
            #pragma unroll
            for (int n = 0; n < 4; n++) {
                FragB bf;
                wmma::load_matrix_sync(bf, Bl + ko*LDA + c0 + n*16, LDA);
                wmma::mma_sync(acc[0][n], aH0, bf, acc[0][n]);
                wmma::mma_sync(acc[1][n], aH1, bf, acc[1][n]);
            }
        }
        __syncthreads();   // A region dead; safe to overlay hloc/hbuf

        // store: cols<64 -> hloc (ldm 72), cols>=64 -> hbuf (ldm 68)
        #pragma unroll
        for (int i = 0; i < 2; i++) {
            #pragma unroll
            for (int n = 0; n < 4; n++) {
                int rr = r0 + 16*i, cc = c0 + 16*n;
                if (cc < 64)
                    wmma::store_matrix_sync(hloc + (size_t)rr*LDH + cc, acc[i][n],
                                            LDH, wmma::mem_row_major);
                else
                    wmma::store_matrix_sync(hbuf + (size_t)rr*LDB2 + (cc - 64), acc[i][n],
                                            LDB2, wmma::mem_row_major);
            }
        }
    }
    __syncthreads();

    // in-place bias + gelu (32 values per thread per half)
    #pragma unroll 4
    for (int idx = t; idx < 8192; idx += 256) {
        int r = idx >> 6, c = idx & 63;
        hloc[r*LDH + c]  = gelu_exact(hloc[r*LDH + c]  + b1s[c]);
        hbuf[r*LDB2 + c] = gelu_exact(hbuf[r*LDB2 + c] + b1s[64 + c]);
    }
    __syncthreads();

    // glob partials from hbuf (128 rows)
    {
        int g0 = R0 / RR;
        int bnd = (g0 + 1)*RR - R0;
        if (bnd > 128) bnd = 128;
        if (t < 128) {
            int side = t >> 6, col = t & 63;
            int r0 = side ? bnd : 0;
            int r1 = side ? 128 : bnd;
            float s = 0.0f;
            for (int r = r0; r < r1; r++) s += hbuf[r*LDB2 + col];
            g_part[blockIdx.x*128 + side*64 + col] = s;
        }
    }

    // stage-2 GEMM (FFMA2): hloc[128x64] @ w2t -> g_acc32
    {
        const int ty = t >> 4, tx = t & 15;     // rows ty*8..+7, cols {tx, tx+16}
        u64 acc2[8][2];
        #pragma unroll
        for (int i = 0; i < 8; i++) { acc2[i][0] = 0ULL; acc2[i][1] = 0ULL; }
        const u64* hu   = (const u64*)hloc;     // row stride 36 u64 (LDH=72)
        const u64* w2u0 = (const u64*)(w2t + tx*66);
        const u64* w2u1 = (const u64*)(w2t + (tx+16)*66);
        #pragma unroll 4
        for (int k2 = 0; k2 < 32; k2++) {
            u64 b0 = w2u0[k2], b1v = w2u1[k2];
            #pragma unroll
            for (int i = 0; i < 8; i++) {
                u64 a = hu[(ty*8 + i)*36 + k2];
                acc2[i][0] = fma2(a, b0,  acc2[i][0]);
                acc2[i][1] = fma2(a, b1v, acc2[i][1]);
            }
        }
        #pragma unroll
        for (int i = 0; i < 8; i++) {
            size_t rg = (size_t)(R0 + ty*8 + i);
            float lo, hi;
            upk2(acc2[i][0], lo, hi);
            g_acc32[rg*32 + tx]      = lo + hi;
            upk2(acc2[i][1], lo, hi);
            g_acc32[rg*32 + tx + 16] = lo + hi;
        }
    }
}

// ---------------------------------------------------------------------------
// Kernel glob: combine per-tile partials -> mean -> glob @ w2[64:,:].
// (128-row tiles.)
// ---------------------------------------------------------------------------
__global__ void __launch_bounds__(64) k_glob(const float* __restrict__ w2)
{
    __shared__ float gl[64];
    const int g = blockIdx.x, c = threadIdx.x;
    const int b_start = (g * RR) >> 7;
    const int b_end   = (g * RR + RR - 1) >> 7;
    float s = 0.0f;
    for (int b = b_start; b <= b_end; b++) {
        int side = g - (b * 128) / RR;    // 0 or 1 by construction
        s += g_part[b*128 + side*64 + c];
    }
    gl[c] = s * (1.0f/374.0f);
    __syncthreads();
    if (c < 32) {
        float a = 0.0f;
        #pragma unroll
        for (int k = 0; k < 64; k++) a += gl[k] * w2[(64 + k)*32 + c];
        g_gcon[g*32 + c] = a;
    }
}

// ---------------------------------------------------------------------------
// Kernel 2 (elementwise): gelu(acc32 + gcon + b2) -> w3 head -> softmax ->
// score + Gumbel -> g_scores.
// ---------------------------------------------------------------------------
__global__ void __launch_bounds__(256) k2_scores(
    const float* __restrict__ b2, const float* __restrict__ w3,
    const float* __restrict__ b3, const float* __restrict__ u)
{
    __shared__ float b2s[32];
    __shared__ float w3s[64];
    __shared__ float b3s[2];
    const int t = threadIdx.x;
    if (t < 32) b2s[t] = b2[t];
    if (t < 64) w3s[t] = w3[t];
    if (t < 2)  b3s[t] = b3[t];
    __syncthreads();

    const int e = blockIdx.x*256 + t;
    if (e >= NROWS) return;
    const int bt = e / RR;
    const float* gc = g_gcon + bt*32;

    float z0 = b3s[0], z1 = b3s[1];
    const float4* ap = (const float4*)(g_acc32 + (size_t)e*32);
    #pragma unroll
    for (int q = 0; q < 8; q++) {
        float4 a = ap[q];
        int c = q*4;
        float h0 = gelu_exact(a.x + b2s[c]   + gc[c]);
        float h1 = gelu_exact(a.y + b2s[c+1] + gc[c+1]);
        float h2 = gelu_exact(a.z + b2s[c+2] + gc[c+2]);
        float h3 = gelu_exact(a.w + b2s[c+3] + gc[c+3]);
        z0 += h0*w3s[2*c]   + h1*w3s[2*c+2] + h2*w3s[2*c+4] + h3*w3s[2*c+6];
        z1 += h0*w3s[2*c+1] + h1*w3s[2*c+3] + h2*w3s[2*c+5] + h3*w3s[2*c+7];
    }
    float m  = fmaxf(z0, z1);
    float e0 = expf(z0 - m), e1 = expf(z1 - m);
    float score = e1 / (e0 + e1);
    float uu  = u[e];
    float gum = -logf(-logf(uu));
    g_scores[e] = score + gum;
}

// ---------------------------------------------------------------------------
// Kernel 3: 299-step subset-operator scan, one warp per (b,t).
// ---------------------------------------------------------------------------
__global__ void __launch_bounds__(32) k3_scan(float* __restrict__ out)
{
    const int bt = blockIdx.x, lane = threadIdx.x;

    float ex[12], kh[12];
    #pragma unroll
    for (int j = 0; j < 12; j++) {
        int idx = j*32 + lane;
        ex[j] = (idx < RR) ? expf(g_scores[(size_t)bt*RR + idx]) : 0.0f;
        kh[j] = 0.0f;
    }

    #pragma unroll 1
    for (int it = 0; it < KSEL - 1; it++) {
        float z = (((ex[0] + ex[1]) + (ex[2] + ex[3])) +
                   ((ex[4] + ex[5]) + (ex[6] + ex[7]))) +
                  ((ex[8] + ex[9]) + (ex[10] + ex[11]));
        #pragma unroll
        for (int o = 16; o; o >>= 1) z += __shfl_xor_sync(0xffffffffu, z, o);
        float rinv = frcp(z);
        #pragma unroll
        for (int j = 0; j < 12; j++) {
            kh[j] = fmaf(ex[j], rinv, kh[j]);
            float m = fmaxf(fmaf(-ex[j], rinv, 1.0f), EPS_TINY);
            ex[j] *= m;
        }
    }
    {
        float z = (((ex[0] + ex[1]) + (ex[2] + ex[3])) +
                   ((ex[4] + ex[5]) + (ex[6] + ex[7]))) +
                  ((ex[8] + ex[9]) + (ex[10] + ex[11]));
        #pragma unroll
        for (int o = 16; o; o >>= 1) z += __shfl_xor_sync(0xffffffffu, z, o);
        float rinv = frcp(z);
        #pragma unroll
        for (int j = 0; j < 12; j++) kh[j] = fmaf(ex[j], rinv, kh[j]);
    }

    #pragma unroll
    for (int j = 0; j < 12; j++) {
        int idx = j*32 + lane;
        if (idx < RR) out[(size_t)bt*RR + idx] = kh[j];
    }
}

// ---------------------------------------------------------------------------
// Kernel 4: stable top-K rank (value desc, ties -> lower index).
// ---------------------------------------------------------------------------
__global__ void __launch_bounds__(384) k4_rank(float* __restrict__ out)
{
    __shared__ float ks[RR];
    const int bt = blockIdx.x, t = threadIdx.x;
    if (t < RR) ks[t] = out[(size_t)bt*RR + t];
    __syncthreads();
    if (t >= RR) return;
    const float mine = ks[t];
    int rank = 0;
    #pragma unroll 4
    for (int i = 0; i < RR; i++) {
        float kv = ks[i];
        rank += (kv > mine) || (kv == mine && i < t);
    }
    if (rank < KSEL)
        out[(size_t)NROWS + (size_t)bt*KSEL + rank] = (float)t;
}

// ---------------------------------------------------------------------------
extern "C" void kernel_launch(void* const* d_in, const int* in_sizes, int n_in,
                              void* d_out, int out_size)
{
    const float* x   = (const float*)d_in[0];
    const float* u   = (const float*)d_in[1];
    const float* lnw = (const float*)d_in[2];
    const float* lnb = (const float*)d_in[3];
    const float* w1  = (const float*)d_in[4];
    const float* b1  = (const float*)d_in[5];
    const float* w2  = (const float*)d_in[6];
    const float* b2  = (const float*)d_in[7];
    const float* w3  = (const float*)d_in[8];
    const float* b3  = (const float*)d_in[9];
    float* out = (float*)d_out;

    cudaFuncSetAttribute(k1_ln_gemm1, cudaFuncAttributeMaxDynamicSharedMemorySize,
                         SM_TOTAL);

    k0_split_w1<<<64, 256>>>(w1);
    k1_ln_gemm1<<<NBLK1, 256, SM_TOTAL>>>(x, lnw, lnb, b1, w2);
    k_glob<<<BT, 64>>>(w2);
    k2_scores<<<(NROWS + 255)/256, 256>>>(b2, w3, b3, u);
    k3_scan<<<BT, 32>>>(out);
    k4_rank<<<BT, 384>>>(out);
}